// round 1
// baseline (speedup 1.0000x reference)
#include <cuda_runtime.h>

#define N_NODES 10000
#define N_EDGES 100000
#define F 64
#define NTYPES 10
#define WT_ELEMS (NTYPES * F * F)   // 40960 floats = 160KB

__device__ float g_deg_out[N_NODES];
__device__ float g_deg_in[N_NODES];

// Kernel 1: zero the output accumulator and both degree arrays.
__global__ void rconv_init(float* __restrict__ acc) {
    int stride = gridDim.x * blockDim.x;
    for (int i = blockIdx.x * blockDim.x + threadIdx.x; i < N_NODES * F; i += stride)
        acc[i] = 0.0f;
    for (int j = blockIdx.x * blockDim.x + threadIdx.x; j < N_NODES; j += stride) {
        g_deg_out[j] = 0.0f;
        g_deg_in[j]  = 0.0f;
    }
}

// Kernel 2: per-edge degree counting.
__global__ void rconv_count(const int* __restrict__ src, const int* __restrict__ dst) {
    int e = blockIdx.x * blockDim.x + threadIdx.x;
    if (e < N_EDGES) {
        atomicAdd(&g_deg_out[src[e]], 1.0f);
        atomicAdd(&g_deg_in[dst[e]], 1.0f);
    }
}

// Kernel 3: main edge kernel. One warp per edge (grid-stride).
// All 10 relation matrices staged in smem TRANSPOSED: wt[r][i][o], so that at
// fixed input index i, lanes read consecutive floats over the output index o
// -> conflict-free LDS. h_src held in registers (2 floats/lane), broadcast via
// shfl. Each lane produces outputs {lane, lane+32}, scattered with atomicAdd.
__global__ __launch_bounds__(512, 1) void rconv_edges(
    const float* __restrict__ feat,
    const int*   __restrict__ src,
    const int*   __restrict__ dst,
    const int*   __restrict__ order,
    const float* __restrict__ emb,
    float*       __restrict__ acc)
{
    extern __shared__ float wt[];  // [NTYPES][F][F] : wt[r][i][o]
    // Cooperative load + transpose: emb[r][o*F + i] -> wt[r][i*F + o]
    for (int idx = threadIdx.x; idx < WT_ELEMS; idx += blockDim.x) {
        int r   = idx >> 12;          // /4096
        int rem = idx & 4095;
        int o   = rem >> 6;
        int i   = rem & 63;
        wt[(r << 12) + (i << 6) + o] = emb[idx];
    }
    __syncthreads();

    const int lane   = threadIdx.x & 31;
    const int warp   = (blockIdx.x * blockDim.x + threadIdx.x) >> 5;
    const int nwarps = (gridDim.x * blockDim.x) >> 5;

    for (int e = warp; e < N_EDGES; e += nwarps) {
        const int s = __ldg(&src[e]);
        const int d = __ldg(&dst[e]);
        const int r = __ldg(&order[e]);

        const float scale = rsqrtf(fmaxf(g_deg_out[s], 1.0f));
        const float h0 = __ldg(&feat[s * F + lane])      * scale;
        const float h1 = __ldg(&feat[s * F + lane + 32]) * scale;

        const float* __restrict__ w = &wt[r << 12];
        float a0 = 0.0f, a1 = 0.0f;
        #pragma unroll
        for (int i = 0; i < 32; i++) {
            const float hi = __shfl_sync(0xffffffffu, h0, i);
            a0 = fmaf(w[(i << 6) + lane],      hi, a0);
            a1 = fmaf(w[(i << 6) + lane + 32], hi, a1);
        }
        #pragma unroll
        for (int i = 0; i < 32; i++) {
            const float hi = __shfl_sync(0xffffffffu, h1, i);
            a0 = fmaf(w[((i + 32) << 6) + lane],      hi, a0);
            a1 = fmaf(w[((i + 32) << 6) + lane + 32], hi, a1);
        }
        atomicAdd(&acc[d * F + lane],      a0);
        atomicAdd(&acc[d * F + lane + 32], a1);
    }
}

// Kernel 4: post-norm by in_deg^{-1/2} and add bias.
__global__ void rconv_final(float* __restrict__ out, const float* __restrict__ bias) {
    int stride = gridDim.x * blockDim.x;
    for (int i = blockIdx.x * blockDim.x + threadIdx.x; i < N_NODES * F; i += stride) {
        int n = i >> 6;
        int f = i & 63;
        float s = rsqrtf(fmaxf(g_deg_in[n], 1.0f));
        out[i] = out[i] * s + bias[f];
    }
}

extern "C" void kernel_launch(void* const* d_in, const int* in_sizes, int n_in,
                              void* d_out, int out_size) {
    const float* feat = (const float*)d_in[0];
    const int*   src  = (const int*)  d_in[1];
    const int*   dst  = (const int*)  d_in[2];
    const int*   ordr = (const int*)  d_in[3];
    const float* emb  = (const float*)d_in[4];
    const float* bias = (const float*)d_in[5];
    float* out = (float*)d_out;

    static bool attr_set = false;
    if (!attr_set) {
        cudaFuncSetAttribute(rconv_edges,
                             cudaFuncAttributeMaxDynamicSharedMemorySize,
                             WT_ELEMS * (int)sizeof(float));
        attr_set = true;
    }

    rconv_init<<<512, 256>>>(out);
    rconv_count<<<(N_EDGES + 255) / 256, 256>>>(src, dst);
    rconv_edges<<<148, 512, WT_ELEMS * (int)sizeof(float)>>>(feat, src, dst, ordr, emb, out);
    rconv_final<<<512, 256>>>(out, bias);
}

// round 3
// speedup vs baseline: 1.3933x; 1.3933x over previous
#include <cuda_runtime.h>

#define N_NODES 10000
#define N_EDGES 100000
#define F 64
#define NTYPES 10
#define WT_ELEMS (NTYPES * F * F)   // 40960 floats = 160KB
#define GRP 8                        // edges per warp group (same relation type)

// ---- device scratch (no allocs allowed) ----
__device__ float g_deg_out[N_NODES];
__device__ float g_deg_in[N_NODES];
__device__ float g_featn[N_NODES * F];   // prescaled features
__device__ int   g_esrc[N_EDGES];        // sorted-by-type src
__device__ int   g_edst[N_EDGES];        // sorted-by-type dst
__device__ int   g_hist[NTYPES];
__device__ int   g_cursor[NTYPES];

// ------------------------------------------------------------------
// Kernel 1: zero accumulator, degrees, histogram, cursors.
__global__ void rconv_init(float4* __restrict__ acc4) {
    int stride = gridDim.x * blockDim.x;
    int tid = blockIdx.x * blockDim.x + threadIdx.x;
    for (int i = tid; i < N_NODES * F / 4; i += stride) acc4[i] = make_float4(0.f, 0.f, 0.f, 0.f);
    for (int j = tid; j < N_NODES; j += stride) { g_deg_out[j] = 0.f; g_deg_in[j] = 0.f; }
    if (tid < NTYPES) { g_hist[tid] = 0; g_cursor[tid] = 0; }
}

// ------------------------------------------------------------------
// Kernel 2: degrees + relation-type histogram (smem-staged).
__global__ void rconv_count(const int* __restrict__ src, const int* __restrict__ dst,
                            const int* __restrict__ order) {
    __shared__ int sh[NTYPES];
    if (threadIdx.x < NTYPES) sh[threadIdx.x] = 0;
    __syncthreads();
    int stride = gridDim.x * blockDim.x;
    for (int e = blockIdx.x * blockDim.x + threadIdx.x; e < N_EDGES; e += stride) {
        atomicAdd(&g_deg_out[src[e]], 1.0f);
        atomicAdd(&g_deg_in[dst[e]], 1.0f);
        atomicAdd(&sh[order[e]], 1);
    }
    __syncthreads();
    if (threadIdx.x < NTYPES) atomicAdd(&g_hist[threadIdx.x], sh[threadIdx.x]);
}

// ------------------------------------------------------------------
// Kernel 3: prescale features by out_deg^{-1/2}.
__global__ void rconv_prescale(const float2* __restrict__ feat2) {
    int i = blockIdx.x * blockDim.x + threadIdx.x;   // over N_NODES*32 float2
    if (i < N_NODES * (F / 2)) {
        int n = i >> 5;
        float s = rsqrtf(fmaxf(g_deg_out[n], 1.0f));
        float2 v = feat2[i];
        ((float2*)g_featn)[i] = make_float2(v.x * s, v.y * s);
    }
}

// ------------------------------------------------------------------
// Kernel 4: counting-sort scatter. Each block handles a contiguous edge
// chunk: local smem histogram -> reserve per-type ranges with ONE global
// atomic per type -> place (src,dst) into type-sorted arrays.
__global__ void rconv_scatter(const int* __restrict__ src, const int* __restrict__ dst,
                              const int* __restrict__ order) {
    __shared__ int sh_cnt[NTYPES];
    __shared__ int sh_base[NTYPES];
    __shared__ int sh_off[NTYPES];
    const int per_blk = (N_EDGES + gridDim.x - 1) / gridDim.x;
    const int e0 = blockIdx.x * per_blk;
    const int e1 = min(e0 + per_blk, N_EDGES);

    if (threadIdx.x < NTYPES) sh_cnt[threadIdx.x] = 0;
    __syncthreads();
    for (int e = e0 + threadIdx.x; e < e1; e += blockDim.x)
        atomicAdd(&sh_cnt[order[e]], 1);
    __syncthreads();
    if (threadIdx.x == 0) {
        int a = 0;
        for (int t = 0; t < NTYPES; t++) { sh_off[t] = a; a += g_hist[t]; }
    }
    __syncthreads();
    if (threadIdx.x < NTYPES) {
        int t = threadIdx.x;
        sh_base[t] = sh_off[t] + atomicAdd(&g_cursor[t], sh_cnt[t]);
        sh_cnt[t] = 0;
    }
    __syncthreads();
    for (int e = e0 + threadIdx.x; e < e1; e += blockDim.x) {
        int t = order[e];
        int pos = sh_base[t] + atomicAdd(&sh_cnt[t], 1);
        g_esrc[pos] = src[e];
        g_edst[pos] = dst[e];
    }
}

// ------------------------------------------------------------------
// Kernel 5: main edge kernel. All 10 W matrices staged transposed in smem
// (wt[r][i][o]). Warps process groups of 8 same-type edges; W rows are read
// once per group (8x less LDS traffic). Lane L owns outputs {2L, 2L+1} so
// weight reads are conflict-free LDS.64 and feature gathers are LDG.64.
__global__ __launch_bounds__(1024, 1) void rconv_edges(
    const float* __restrict__ emb, float* __restrict__ acc)
{
    extern __shared__ float wt[];  // [NTYPES][F][F] : wt[r][i][o]
    for (int idx = threadIdx.x; idx < WT_ELEMS; idx += blockDim.x) {
        int r = idx >> 12, rem = idx & 4095, o = rem >> 6, i = rem & 63;
        wt[(r << 12) + (i << 6) + o] = emb[idx];
    }
    __shared__ int s_off[NTYPES + 1];
    __shared__ int s_goff[NTYPES + 1];
    if (threadIdx.x == 0) {
        int a = 0, g = 0;
        for (int t = 0; t < NTYPES; t++) {
            s_off[t] = a; s_goff[t] = g;
            int h = g_hist[t];
            a += h; g += (h + GRP - 1) / GRP;
        }
        s_off[NTYPES] = a; s_goff[NTYPES] = g;
    }
    __syncthreads();

    const int lane = threadIdx.x & 31;
    const int warp = (blockIdx.x * blockDim.x + threadIdx.x) >> 5;
    const int nwarps = (gridDim.x * blockDim.x) >> 5;
    const int n_groups = s_goff[NTYPES];
    const float2* __restrict__ featn2 = (const float2*)g_featn;

    for (int gi = warp; gi < n_groups; gi += nwarps) {
        int t = 0;
        while (gi >= s_goff[t + 1]) t++;
        const int base = s_off[t] + (gi - s_goff[t]) * GRP;
        const int lim = s_off[t + 1];

        float2 h[GRP];
        int dd[GRP];
        bool va[GRP];
        #pragma unroll
        for (int k = 0; k < GRP; k++) {
            va[k] = (base + k) < lim;
            int idx = va[k] ? (base + k) : base;
            int s = g_esrc[idx];
            dd[k] = g_edst[idx];
            float2 v = featn2[s * 32 + lane];
            h[k] = va[k] ? v : make_float2(0.f, 0.f);
        }

        const float2* __restrict__ w2 = (const float2*)&wt[t << 12];
        float2 a[GRP];
        #pragma unroll
        for (int k = 0; k < GRP; k++) a[k] = make_float2(0.f, 0.f);

        #pragma unroll
        for (int i = 0; i < 32; i++) {
            const float2 wlo = w2[(2 * i) * 32 + lane];       // row 2i,   cols 2L..2L+1
            const float2 whi = w2[(2 * i + 1) * 32 + lane];   // row 2i+1
            #pragma unroll
            for (int k = 0; k < GRP; k++) {
                const float hx = __shfl_sync(0xffffffffu, h[k].x, i);  // h[2i]
                const float hy = __shfl_sync(0xffffffffu, h[k].y, i);  // h[2i+1]
                a[k].x = fmaf(wlo.x, hx, fmaf(whi.x, hy, a[k].x));
                a[k].y = fmaf(wlo.y, hx, fmaf(whi.y, hy, a[k].y));
            }
        }

        #pragma unroll
        for (int k = 0; k < GRP; k++) {
            if (va[k]) {
                float* p = &acc[dd[k] * F + 2 * lane];
                atomicAdd(p, a[k].x);
                atomicAdd(p + 1, a[k].y);
            }
        }
    }
}

// ------------------------------------------------------------------
// Kernel 6: post-norm by in_deg^{-1/2} + bias (float4 vectorized).
__global__ void rconv_final(float4* __restrict__ out4, const float4* __restrict__ bias4) {
    int i = blockIdx.x * blockDim.x + threadIdx.x;   // over N_NODES*16 float4
    if (i < N_NODES * (F / 4)) {
        int n = i >> 4, f4 = i & 15;
        float s = rsqrtf(fmaxf(g_deg_in[n], 1.0f));
        float4 v = out4[i], b = bias4[f4];
        out4[i] = make_float4(v.x * s + b.x, v.y * s + b.y, v.z * s + b.z, v.w * s + b.w);
    }
}

extern "C" void kernel_launch(void* const* d_in, const int* in_sizes, int n_in,
                              void* d_out, int out_size) {
    const float* feat = (const float*)d_in[0];
    const int*   src  = (const int*)  d_in[1];
    const int*   dst  = (const int*)  d_in[2];
    const int*   ordr = (const int*)  d_in[3];
    const float* emb  = (const float*)d_in[4];
    const float* bias = (const float*)d_in[5];
    float* out = (float*)d_out;

    static bool attr_set = false;
    if (!attr_set) {
        cudaFuncSetAttribute(rconv_edges,
                             cudaFuncAttributeMaxDynamicSharedMemorySize,
                             WT_ELEMS * (int)sizeof(float));
        attr_set = true;
    }

    rconv_init<<<256, 256>>>((float4*)out);
    rconv_count<<<(N_EDGES + 511) / 512, 512>>>(src, dst, ordr);
    rconv_prescale<<<(N_NODES * (F / 2) + 255) / 256, 256>>>((const float2*)feat);
    rconv_scatter<<<64, 256>>>(src, dst, ordr);
    rconv_edges<<<148, 1024, WT_ELEMS * (int)sizeof(float)>>>(emb, out);
    rconv_final<<<(N_NODES * (F / 4) + 255) / 256, 256>>>((float4*)out, (const float4*)bias);
}

// round 4
// speedup vs baseline: 1.4247x; 1.0226x over previous
#include <cuda_runtime.h>
#include <cstdint>

#define N_NODES 10000
#define N_EDGES 100000
#define F 64
#define NTYPES 10
#define WT_ELEMS (NTYPES * F * F)   // 40960 floats = 160KB
#define GRP 8                        // edges per warp group (same relation type)

// ---- device scratch (no allocs allowed) ----
__device__ float g_deg_out[N_NODES];
__device__ float g_deg_in[N_NODES];
__device__ float g_featn[N_NODES * F];   // prescaled features
__device__ int   g_esrc[N_EDGES];        // sorted-by-type src
__device__ int   g_edst[N_EDGES];        // sorted-by-type dst
__device__ int   g_hist[NTYPES];
__device__ int   g_cursor[NTYPES];

// ------------------------------------------------------------------
// Kernel 1: zero accumulator, degrees, histogram, cursors.
__global__ void rconv_init(float4* __restrict__ acc4) {
    int stride = gridDim.x * blockDim.x;
    int tid = blockIdx.x * blockDim.x + threadIdx.x;
    for (int i = tid; i < N_NODES * F / 4; i += stride) acc4[i] = make_float4(0.f, 0.f, 0.f, 0.f);
    for (int j = tid; j < N_NODES; j += stride) { g_deg_out[j] = 0.f; g_deg_in[j] = 0.f; }
    if (tid < NTYPES) { g_hist[tid] = 0; g_cursor[tid] = 0; }
}

// ------------------------------------------------------------------
// Kernel 2: degrees + relation-type histogram (warp-aggregated smem atomics).
__global__ void rconv_count(const int* __restrict__ src, const int* __restrict__ dst,
                            const int* __restrict__ order) {
    __shared__ int sh[NTYPES];
    if (threadIdx.x < NTYPES) sh[threadIdx.x] = 0;
    __syncthreads();
    const int lane = threadIdx.x & 31;
    int stride = gridDim.x * blockDim.x;
    int tid = blockIdx.x * blockDim.x + threadIdx.x;
    // uniform trip count per warp so ballots are safe
    for (int e0 = tid - lane; e0 - (tid - lane) + (tid - lane) < N_EDGES; e0 += stride) {
        int e = e0 + lane;
        bool v = e < N_EDGES;
        unsigned act = __ballot_sync(0xffffffffu, v);
        if (v) {
            atomicAdd(&g_deg_out[src[e]], 1.0f);
            atomicAdd(&g_deg_in[dst[e]], 1.0f);
            int t = order[e];
            unsigned m = __match_any_sync(act, t);
            if ((m & ((1u << lane) - 1)) == 0)       // leader of the type group
                atomicAdd(&sh[t], __popc(m));
        }
        if (e0 + stride - (tid - lane) >= N_EDGES && e0 >= N_EDGES) break;
        if (e0 + stride >= N_EDGES + stride) break;  // safety (unreachable)
        if (e0 + stride - lane >= N_EDGES && false) break;
        if (e0 + stride >= 0 && e0 + stride - (e0 + stride) != 0) break; // no-op
        if (e0 + stride >= N_EDGES && (e0 + stride) - lane >= N_EDGES) { /*continue to loop cond*/ }
        if (e0 + stride >= N_EDGES + 32) break;
    }
    __syncthreads();
    if (threadIdx.x < NTYPES) atomicAdd(&g_hist[threadIdx.x], sh[threadIdx.x]);
}

// ------------------------------------------------------------------
// Kernel 3: prescale features by out_deg^{-1/2}.
__global__ void rconv_prescale(const float2* __restrict__ feat2) {
    int i = blockIdx.x * blockDim.x + threadIdx.x;   // over N_NODES*32 float2
    if (i < N_NODES * (F / 2)) {
        int n = i >> 5;
        float s = rsqrtf(fmaxf(g_deg_out[n], 1.0f));
        float2 v = feat2[i];
        ((float2*)g_featn)[i] = make_float2(v.x * s, v.y * s);
    }
}

// ------------------------------------------------------------------
// Kernel 4: counting-sort scatter. Block-local histogram -> one global range
// reservation per type per block -> warp-aggregated placement (one smem
// atomic per same-type lane group instead of per edge).
__global__ void rconv_scatter(const int* __restrict__ src, const int* __restrict__ dst,
                              const int* __restrict__ order) {
    __shared__ int sh_cnt[NTYPES];
    __shared__ int sh_base[NTYPES];
    __shared__ int sh_off[NTYPES];
    const int per_blk = (N_EDGES + gridDim.x - 1) / gridDim.x;
    const int e0 = blockIdx.x * per_blk;
    const int e1 = min(e0 + per_blk, N_EDGES);
    const int nloc = e1 - e0;
    const int lane = threadIdx.x & 31;

    if (threadIdx.x < NTYPES) sh_cnt[threadIdx.x] = 0;
    __syncthreads();

    // Phase 1: local histogram (warp-aggregated)
    for (int b = 0; b < nloc; b += blockDim.x) {
        int idx = b + threadIdx.x;
        bool v = idx < nloc;
        unsigned act = __ballot_sync(0xffffffffu, v);
        if (v) {
            int t = order[e0 + idx];
            unsigned m = __match_any_sync(act, t);
            if ((m & ((1u << lane) - 1)) == 0)
                atomicAdd(&sh_cnt[t], __popc(m));
        }
    }
    __syncthreads();

    // Phase 2: reserve global ranges
    if (threadIdx.x == 0) {
        int a = 0;
        for (int t = 0; t < NTYPES; t++) { sh_off[t] = a; a += g_hist[t]; }
    }
    __syncthreads();
    if (threadIdx.x < NTYPES) {
        int t = threadIdx.x;
        sh_base[t] = sh_off[t] + atomicAdd(&g_cursor[t], sh_cnt[t]);
        sh_cnt[t] = 0;
    }
    __syncthreads();

    // Phase 3: placement (warp-aggregated rank within type group)
    for (int b = 0; b < nloc; b += blockDim.x) {
        int idx = b + threadIdx.x;
        bool v = idx < nloc;
        unsigned act = __ballot_sync(0xffffffffu, v);
        if (v) {
            int e = e0 + idx;
            int t = order[e];
            unsigned m = __match_any_sync(act, t);
            int leader = __ffs(m) - 1;
            int rank = __popc(m & ((1u << lane) - 1));
            int gbase = 0;
            if (lane == leader) gbase = atomicAdd(&sh_cnt[t], __popc(m));
            gbase = __shfl_sync(m, gbase, leader);
            int pos = sh_base[t] + gbase + rank;
            g_esrc[pos] = src[e];
            g_edst[pos] = dst[e];
        }
    }
}

// ------------------------------------------------------------------
// Kernel 5: main edge kernel. W staged transposed in smem (wt[r][i][o]).
// Warps process 8 same-type edges; lane owns output cols {2L,2L+1}.
// Inner product uses packed fma.rn.f32x2 (FFMA2) — halves FMA-pipe work.
// Epilogue pairs lanes and issues red.global.add.v4.f32 (4x fewer L2 atomics).
__global__ __launch_bounds__(768, 1) void rconv_edges(
    const float* __restrict__ emb, float* __restrict__ acc)
{
    extern __shared__ float wt[];  // [NTYPES][F][F] : wt[r][i][o]
    for (int idx = threadIdx.x; idx < WT_ELEMS; idx += blockDim.x) {
        int r = idx >> 12, rem = idx & 4095, o = rem >> 6, i = rem & 63;
        wt[(r << 12) + (i << 6) + o] = emb[idx];
    }
    __shared__ int s_off[NTYPES + 1];
    __shared__ int s_goff[NTYPES + 1];
    if (threadIdx.x == 0) {
        int a = 0, g = 0;
        for (int t = 0; t < NTYPES; t++) {
            s_off[t] = a; s_goff[t] = g;
            int h = g_hist[t];
            a += h; g += (h + GRP - 1) / GRP;
        }
        s_off[NTYPES] = a; s_goff[NTYPES] = g;
    }
    __syncthreads();

    const int lane = threadIdx.x & 31;
    const int warp = (blockIdx.x * blockDim.x + threadIdx.x) >> 5;
    const int nwarps = (gridDim.x * blockDim.x) >> 5;
    const int n_groups = s_goff[NTYPES];
    const float2* __restrict__ featn2 = (const float2*)g_featn;

    for (int gi = warp; gi < n_groups; gi += nwarps) {
        int t = 0;
        while (gi >= s_goff[t + 1]) t++;
        const int base = s_off[t] + (gi - s_goff[t]) * GRP;
        const int lim = s_off[t + 1];

        float2 h[GRP];
        int dd[GRP];
        bool va[GRP];
        #pragma unroll
        for (int k = 0; k < GRP; k++) {
            va[k] = (base + k) < lim;
            int idx = va[k] ? (base + k) : base;
            int s = g_esrc[idx];
            dd[k] = g_edst[idx];
            float2 v = featn2[s * 32 + lane];
            h[k] = va[k] ? v : make_float2(0.f, 0.f);
        }

        const float2* __restrict__ w2 = (const float2*)&wt[t << 12];
        uint64_t a2[GRP];
        #pragma unroll
        for (int k = 0; k < GRP; k++) a2[k] = 0ull;

        #pragma unroll
        for (int i = 0; i < F; i++) {
            // wpk = packed {w[i][2L], w[i][2L+1]}
            const float2 wp = w2[i * 32 + lane];
            uint64_t wpk;
            asm("mov.b64 %0, {%1, %2};" : "=l"(wpk) : "f"(wp.x), "f"(wp.y));
            #pragma unroll
            for (int k = 0; k < GRP; k++) {
                const float hv = __shfl_sync(0xffffffffu,
                                             (i & 1) ? h[k].y : h[k].x, i >> 1);
                uint64_t hpk;
                asm("mov.b64 %0, {%1, %1};" : "=l"(hpk) : "f"(hv));
                asm("fma.rn.f32x2 %0, %1, %2, %0;" : "+l"(a2[k]) : "l"(wpk), "l"(hpk));
            }
        }

        #pragma unroll
        for (int k = 0; k < GRP; k++) {
            float ax, ay;
            asm("mov.b64 {%0, %1}, %2;" : "=f"(ax), "=f"(ay) : "l"(a2[k]));
            // pair lanes: even lane gathers odd neighbor's float2 -> red.v4
            float bx = __shfl_down_sync(0xffffffffu, ax, 1);
            float by = __shfl_down_sync(0xffffffffu, ay, 1);
            if (va[k] && !(lane & 1)) {
                float* p = &acc[dd[k] * F + 2 * lane];
                asm volatile("red.global.add.v4.f32 [%0], {%1, %2, %3, %4};"
                             :: "l"(p), "f"(ax), "f"(ay), "f"(bx), "f"(by)
                             : "memory");
            }
        }
    }
}

// ------------------------------------------------------------------
// Kernel 6: post-norm by in_deg^{-1/2} + bias (float4 vectorized).
__global__ void rconv_final(float4* __restrict__ out4, const float4* __restrict__ bias4) {
    int i = blockIdx.x * blockDim.x + threadIdx.x;   // over N_NODES*16 float4
    if (i < N_NODES * (F / 4)) {
        int n = i >> 4, f4 = i & 15;
        float s = rsqrtf(fmaxf(g_deg_in[n], 1.0f));
        float4 v = out4[i], b = bias4[f4];
        out4[i] = make_float4(v.x * s + b.x, v.y * s + b.y, v.z * s + b.z, v.w * s + b.w);
    }
}

extern "C" void kernel_launch(void* const* d_in, const int* in_sizes, int n_in,
                              void* d_out, int out_size) {
    const float* feat = (const float*)d_in[0];
    const int*   src  = (const int*)  d_in[1];
    const int*   dst  = (const int*)  d_in[2];
    const int*   ordr = (const int*)  d_in[3];
    const float* emb  = (const float*)d_in[4];
    const float* bias = (const float*)d_in[5];
    float* out = (float*)d_out;

    static bool attr_set = false;
    if (!attr_set) {
        cudaFuncSetAttribute(rconv_edges,
                             cudaFuncAttributeMaxDynamicSharedMemorySize,
                             WT_ELEMS * (int)sizeof(float));
        attr_set = true;
    }

    rconv_init<<<256, 256>>>((float4*)out);
    rconv_count<<<(N_EDGES + 511) / 512, 512>>>(src, dst, ordr);
    rconv_prescale<<<(N_NODES * (F / 2) + 255) / 256, 256>>>((const float2*)feat);
    rconv_scatter<<<192, 256>>>(src, dst, ordr);
    rconv_edges<<<148, 768, WT_ELEMS * (int)sizeof(float)>>>(emb, out);
    rconv_final<<<(N_NODES * (F / 4) + 255) / 256, 256>>>((float4*)out, (const float4*)bias);
}

// round 9
// speedup vs baseline: 1.9364x; 1.3591x over previous
#include <cuda_runtime.h>
#include <cstdint>

#define N_NODES 10000
#define N_EDGES 100000
#define F 64
#define NTYPES 10
#define WT_ELEMS (NTYPES * F * F)        // 40960 floats = 160KB
#define GRP 8                             // edges per warp group (same type)
#define EDGE_THREADS 768
#define EDGE_WARPS (EDGE_THREADS / 32)    // 24
#define SH_H_FLOATS (EDGE_WARPS * GRP * F)        // 12288 floats = 48KB
#define SMEM_EDGE_BYTES ((WT_ELEMS + SH_H_FLOATS) * 4)   // 208KB

// ---- device scratch (no allocs allowed) ----
__device__ float g_deg_out[N_NODES];
__device__ float g_deg_in[N_NODES];
__device__ float g_featn[N_NODES * F];   // prescaled features
__device__ int   g_esrc[N_EDGES];        // sorted-by-type src
__device__ int   g_edst[N_EDGES];        // sorted-by-type dst
__device__ int   g_hist[NTYPES];
__device__ int   g_cursor[NTYPES];

// ------------------------------------------------------------------
// Kernel 1: zero accumulator, degrees, histogram, cursors.
__global__ void rconv_init(float4* __restrict__ acc4) {
    int stride = gridDim.x * blockDim.x;
    int tid = blockIdx.x * blockDim.x + threadIdx.x;
    for (int i = tid; i < N_NODES * F / 4; i += stride) acc4[i] = make_float4(0.f, 0.f, 0.f, 0.f);
    for (int j = tid; j < N_NODES; j += stride) { g_deg_out[j] = 0.f; g_deg_in[j] = 0.f; }
    if (tid < NTYPES) { g_hist[tid] = 0; g_cursor[tid] = 0; }
}

// ------------------------------------------------------------------
// Kernel 2: degrees + type histogram. One edge per thread; warp-aggregated
// histogram atomics.
__global__ void rconv_count(const int* __restrict__ src, const int* __restrict__ dst,
                            const int* __restrict__ order) {
    __shared__ int sh[NTYPES];
    if (threadIdx.x < NTYPES) sh[threadIdx.x] = 0;
    __syncthreads();
    const int lane = threadIdx.x & 31;
    int e = blockIdx.x * blockDim.x + threadIdx.x;
    bool v = e < N_EDGES;
    unsigned act = __ballot_sync(0xffffffffu, v);
    if (v) {
        atomicAdd(&g_deg_out[src[e]], 1.0f);
        atomicAdd(&g_deg_in[dst[e]], 1.0f);
        int t = order[e];
        unsigned m = __match_any_sync(act, t);
        if ((m & ((1u << lane) - 1)) == 0)
            atomicAdd(&sh[t], __popc(m));
    }
    __syncthreads();
    if (threadIdx.x < NTYPES) atomicAdd(&g_hist[threadIdx.x], sh[threadIdx.x]);
}

// ------------------------------------------------------------------
// Kernel 3: prescale features by out_deg^{-1/2}.
__global__ void rconv_prescale(const float2* __restrict__ feat2) {
    int i = blockIdx.x * blockDim.x + threadIdx.x;   // over N_NODES*32 float2
    if (i < N_NODES * (F / 2)) {
        int n = i >> 5;
        float s = rsqrtf(fmaxf(g_deg_out[n], 1.0f));
        float2 v = feat2[i];
        ((float2*)g_featn)[i] = make_float2(v.x * s, v.y * s);
    }
}

// ------------------------------------------------------------------
// Kernel 4: counting-sort scatter (block histogram -> one global range
// reservation per type -> warp-aggregated placement).
__global__ void rconv_scatter(const int* __restrict__ src, const int* __restrict__ dst,
                              const int* __restrict__ order) {
    __shared__ int sh_cnt[NTYPES];
    __shared__ int sh_base[NTYPES];
    __shared__ int sh_off[NTYPES];
    const int per_blk = (N_EDGES + gridDim.x - 1) / gridDim.x;
    const int e0 = blockIdx.x * per_blk;
    const int e1 = min(e0 + per_blk, N_EDGES);
    const int nloc = e1 - e0;
    const int lane = threadIdx.x & 31;

    if (threadIdx.x < NTYPES) sh_cnt[threadIdx.x] = 0;
    __syncthreads();

    for (int b = 0; b < nloc; b += blockDim.x) {
        int idx = b + threadIdx.x;
        bool v = idx < nloc;
        unsigned act = __ballot_sync(0xffffffffu, v);
        if (v) {
            int t = order[e0 + idx];
            unsigned m = __match_any_sync(act, t);
            if ((m & ((1u << lane) - 1)) == 0)
                atomicAdd(&sh_cnt[t], __popc(m));
        }
    }
    __syncthreads();

    if (threadIdx.x == 0) {
        int a = 0;
        for (int t = 0; t < NTYPES; t++) { sh_off[t] = a; a += g_hist[t]; }
    }
    __syncthreads();
    if (threadIdx.x < NTYPES) {
        int t = threadIdx.x;
        sh_base[t] = sh_off[t] + atomicAdd(&g_cursor[t], sh_cnt[t]);
        sh_cnt[t] = 0;
    }
    __syncthreads();

    for (int b = 0; b < nloc; b += blockDim.x) {
        int idx = b + threadIdx.x;
        bool v = idx < nloc;
        unsigned act = __ballot_sync(0xffffffffu, v);
        if (v) {
            int e = e0 + idx;
            int t = order[e];
            unsigned m = __match_any_sync(act, t);
            int leader = __ffs(m) - 1;
            int rank = __popc(m & ((1u << lane) - 1));
            int gbase = 0;
            if (lane == leader) gbase = atomicAdd(&sh_cnt[t], __popc(m));
            gbase = __shfl_sync(m, gbase, leader);
            int pos = sh_base[t] + gbase + rank;
            g_esrc[pos] = src[e];
            g_edst[pos] = dst[e];
        }
    }
}

// ------------------------------------------------------------------
// Kernel 5: main edge kernel — NO shuffles.
// W staged in interleaved layout: per type, float4 wv[j][L] =
//   { w[2j][2L], w[2j+1][2L], w[2j][2L+1], w[2j+1][2L+1] }  (j,i = input idx
// pairs, L = lane, lane owns outputs {2L, 2L+1}).
// h vectors for the 8-edge group staged in per-warp smem; inner loop reads
// them as LDS.128 broadcasts. Accumulation packs over K (even/odd input
// halves) so both fma.rn.f32x2 operands come straight out of LDS.128 with
// zero packing instructions. Epilogue: pair lanes -> red.global.add.v4.f32.
__global__ __launch_bounds__(EDGE_THREADS, 1) void rconv_edges(
    const float* __restrict__ emb, float* __restrict__ acc)
{
    extern __shared__ float smem[];
    float* wt  = smem;                 // [NTYPES][32][128] floats (interleaved)
    float* shh = smem + WT_ELEMS;      // [EDGE_WARPS][GRP][64] floats

    // Stage W with the interleave transform.
    for (int idx = threadIdx.x; idx < WT_ELEMS; idx += blockDim.x) {
        int r   = idx >> 12;
        int rem = idx & 4095;
        int j   = rem >> 7;       // input-pair index 0..31
        int pos = rem & 127;
        int L   = pos >> 2;       // lane
        int c   = pos & 3;
        int o   = 2 * L + (c >> 1);
        int i   = 2 * j + (c & 1);
        wt[idx] = emb[(r << 12) + (o << 6) + i];
    }
    __shared__ int s_off[NTYPES + 1];
    __shared__ int s_goff[NTYPES + 1];
    if (threadIdx.x == 0) {
        int a = 0, g = 0;
        for (int t = 0; t < NTYPES; t++) {
            s_off[t] = a; s_goff[t] = g;
            int h = g_hist[t];
            a += h; g += (h + GRP - 1) / GRP;
        }
        s_off[NTYPES] = a; s_goff[NTYPES] = g;
    }
    __syncthreads();

    const int lane   = threadIdx.x & 31;
    const int wl     = threadIdx.x >> 5;
    const int warp   = (blockIdx.x * blockDim.x + threadIdx.x) >> 5;
    const int nwarps = (gridDim.x * blockDim.x) >> 5;
    const int n_groups = s_goff[NTYPES];
    const float2* __restrict__ featn2 = (const float2*)g_featn;
    float2* myh = (float2*)(shh + wl * (GRP * F));   // [GRP][32] float2

    for (int gi = warp; gi < n_groups; gi += nwarps) {
        int t = 0;
        while (gi >= s_goff[t + 1]) t++;
        const int base = s_off[t] + (gi - s_goff[t]) * GRP;
        const int lim  = s_off[t + 1];

        __syncwarp();   // previous iteration's readers done before overwrite
        int dd[GRP];
        #pragma unroll
        for (int k = 0; k < GRP; k++) {
            int idx = min(base + k, lim - 1);
            int s = __ldg(&g_esrc[idx]);
            dd[k] = __ldg(&g_edst[idx]);
            myh[k * 32 + lane] = featn2[s * 32 + lane];
        }
        __syncwarp();

        const ulonglong2* __restrict__ wv = (const ulonglong2*)(wt + (t << 12));
        const ulonglong2* __restrict__ hp = (const ulonglong2*)myh;  // [GRP][16]
        uint64_t a0[GRP], a1[GRP];
        #pragma unroll
        for (int k = 0; k < GRP; k++) { a0[k] = 0ull; a1[k] = 0ull; }

        #pragma unroll
        for (int j2 = 0; j2 < 16; j2++) {
            const ulonglong2 w0 = wv[(2 * j2) * 32 + lane];       // j = 2*j2
            const ulonglong2 w1 = wv[(2 * j2 + 1) * 32 + lane];   // j = 2*j2+1
            #pragma unroll
            for (int k = 0; k < GRP; k++) {
                const ulonglong2 h = hp[k * 16 + j2];   // {h[4j2..4j2+3]} broadcast
                asm("fma.rn.f32x2 %0, %1, %2, %0;" : "+l"(a0[k]) : "l"(w0.x), "l"(h.x));
                asm("fma.rn.f32x2 %0, %1, %2, %0;" : "+l"(a1[k]) : "l"(w0.y), "l"(h.x));
                asm("fma.rn.f32x2 %0, %1, %2, %0;" : "+l"(a0[k]) : "l"(w1.x), "l"(h.y));
                asm("fma.rn.f32x2 %0, %1, %2, %0;" : "+l"(a1[k]) : "l"(w1.y), "l"(h.y));
            }
        }

        #pragma unroll
        for (int k = 0; k < GRP; k++) {
            float p, q, r2, s2;
            asm("mov.b64 {%0, %1}, %2;" : "=f"(p),  "=f"(q)  : "l"(a0[k]));
            asm("mov.b64 {%0, %1}, %2;" : "=f"(r2), "=f"(s2) : "l"(a1[k]));
            float ax = p + q;     // output 2L
            float ay = r2 + s2;   // output 2L+1
            float bx = __shfl_down_sync(0xffffffffu, ax, 1);
            float by = __shfl_down_sync(0xffffffffu, ay, 1);
            if ((base + k) < lim && !(lane & 1)) {
                float* ptr = &acc[dd[k] * F + 2 * lane];
                asm volatile("red.global.add.v4.f32 [%0], {%1, %2, %3, %4};"
                             :: "l"(ptr), "f"(ax), "f"(ay), "f"(bx), "f"(by)
                             : "memory");
            }
        }
    }
}

// ------------------------------------------------------------------
// Kernel 6: post-norm by in_deg^{-1/2} + bias (float4 vectorized).
__global__ void rconv_final(float4* __restrict__ out4, const float4* __restrict__ bias4) {
    int i = blockIdx.x * blockDim.x + threadIdx.x;   // over N_NODES*16 float4
    if (i < N_NODES * (F / 4)) {
        int n = i >> 4, f4 = i & 15;
        float s = rsqrtf(fmaxf(g_deg_in[n], 1.0f));
        float4 v = out4[i], b = bias4[f4];
        out4[i] = make_float4(v.x * s + b.x, v.y * s + b.y, v.z * s + b.z, v.w * s + b.w);
    }
}

extern "C" void kernel_launch(void* const* d_in, const int* in_sizes, int n_in,
                              void* d_out, int out_size) {
    const float* feat = (const float*)d_in[0];
    const int*   src  = (const int*)  d_in[1];
    const int*   dst  = (const int*)  d_in[2];
    const int*   ordr = (const int*)  d_in[3];
    const float* emb  = (const float*)d_in[4];
    const float* bias = (const float*)d_in[5];
    float* out = (float*)d_out;

    static bool attr_set = false;
    if (!attr_set) {
        cudaFuncSetAttribute(rconv_edges,
                             cudaFuncAttributeMaxDynamicSharedMemorySize,
                             SMEM_EDGE_BYTES);
        attr_set = true;
    }

    rconv_init<<<256, 256>>>((float4*)out);
    rconv_count<<<(N_EDGES + 255) / 256, 256>>>(src, dst, ordr);
    rconv_prescale<<<(N_NODES * (F / 2) + 255) / 256, 256>>>((const float2*)feat);
    rconv_scatter<<<256, 512>>>(src, dst, ordr);
    rconv_edges<<<148, EDGE_THREADS, SMEM_EDGE_BYTES>>>(emb, out);
    rconv_final<<<(N_NODES * (F / 4) + 255) / 256, 256>>>((float4*)out, (const float4*)bias);
}

// round 10
// speedup vs baseline: 2.1973x; 1.1348x over previous
#include <cuda_runtime.h>
#include <cstdint>

#define N_NODES 10000
#define N_EDGES 100000
#define F 64
#define NTYPES 10
#define WT_ELEMS (NTYPES * F * F)        // 40960 floats = 160KB
#define GRP 8                             // edges per warp group (same type)
#define SEG_CAP 12288                     // per-type segment capacity (10k avg)
#define EDGE_THREADS 768
#define EDGE_WARPS (EDGE_THREADS / 32)    // 24
#define SH_H_FLOATS (EDGE_WARPS * GRP * F)        // 12288 floats = 48KB
#define SMEM_EDGE_BYTES ((WT_ELEMS + SH_H_FLOATS) * 4)   // 208KB

// ---- device scratch (no allocs allowed) ----
__device__ float g_deg_out[N_NODES];
__device__ float g_deg_in[N_NODES];
__device__ float g_wt[WT_ELEMS];               // pre-interleaved weights
__device__ int   g_esrc[NTYPES * SEG_CAP];     // type-segmented src
__device__ int   g_edst[NTYPES * SEG_CAP];     // type-segmented dst
__device__ int   g_cursor[NTYPES];             // per-type counts

// ------------------------------------------------------------------
// Kernel 1: zero accumulator/degrees/cursors AND pre-interleave W.
// Interleaved layout: per type r, float4 wv[j][L] =
//   { w[2j][2L], w[2j+1][2L], w[2j][2L+1], w[2j+1][2L+1] }
// (j = input pair 0..31, L = lane 0..31; lane owns outputs {2L,2L+1}).
// Scattered emb reads happen ONCE here (coalesced writes), so the edge
// kernel can stage smem with pure float4 copies.
__global__ void rconv_init(float4* __restrict__ acc4, const float* __restrict__ emb) {
    int stride = gridDim.x * blockDim.x;
    int tid = blockIdx.x * blockDim.x + threadIdx.x;
    for (int i = tid; i < N_NODES * F / 4; i += stride)
        acc4[i] = make_float4(0.f, 0.f, 0.f, 0.f);
    for (int j = tid; j < N_NODES; j += stride) { g_deg_out[j] = 0.f; g_deg_in[j] = 0.f; }
    for (int idx = tid; idx < WT_ELEMS; idx += stride) {
        int r   = idx >> 12;
        int rem = idx & 4095;
        int j   = rem >> 7;       // input-pair index 0..31
        int pos = rem & 127;
        int L   = pos >> 2;       // lane
        int c   = pos & 3;
        int o   = 2 * L + (c >> 1);
        int i   = 2 * j + (c & 1);
        g_wt[idx] = emb[(r << 12) + (o << 6) + i];
    }
    if (tid < NTYPES) g_cursor[tid] = 0;
}

// ------------------------------------------------------------------
// Kernel 2: fused degrees + single-pass type-segmented scatter.
// Fixed-capacity segments (base = t*SEG_CAP) eliminate the histogram
// prepass entirely. Warp-aggregated cursor atomics: one global atomic
// per (warp, type) group.
__global__ void rconv_count_scatter(const int* __restrict__ src,
                                    const int* __restrict__ dst,
                                    const int* __restrict__ order) {
    const int lane = threadIdx.x & 31;
    int e = blockIdx.x * blockDim.x + threadIdx.x;
    bool v = e < N_EDGES;
    unsigned act = __ballot_sync(0xffffffffu, v);
    if (v) {
        int s = src[e], d = dst[e], t = order[e];
        atomicAdd(&g_deg_out[s], 1.0f);
        atomicAdd(&g_deg_in[d], 1.0f);
        unsigned m = __match_any_sync(act, t);
        int leader = __ffs(m) - 1;
        int rank = __popc(m & ((1u << lane) - 1));
        int base = 0;
        if (lane == leader) base = atomicAdd(&g_cursor[t], __popc(m));
        base = __shfl_sync(m, base, leader);
        int pos = t * SEG_CAP + base + rank;
        g_esrc[pos] = s;
        g_edst[pos] = d;
    }
}

// ------------------------------------------------------------------
// Kernel 3: main edge kernel — no shuffles in the hot loop.
// Stage pre-interleaved W (coalesced float4), gather h with inline
// out_deg^{-1/2} scaling into per-warp smem, inner product via packed
// fma.rn.f32x2 with both operands straight from LDS.128.
// Epilogue: pair lanes -> red.global.add.v4.f32 (4x fewer L2 atomics).
__global__ __launch_bounds__(EDGE_THREADS, 1) void rconv_edges(
    const float2* __restrict__ feat2, float* __restrict__ acc)
{
    extern __shared__ float smem[];
    float* wt  = smem;                 // [NTYPES][32][128] floats (interleaved)
    float* shh = smem + WT_ELEMS;      // [EDGE_WARPS][GRP][64] floats

    {   // coalesced float4 copy of pre-interleaved weights
        const float4* __restrict__ w4 = (const float4*)g_wt;
        float4* wt4 = (float4*)wt;
        for (int i = threadIdx.x; i < WT_ELEMS / 4; i += blockDim.x)
            wt4[i] = w4[i];
    }
    __shared__ int s_lim[NTYPES];        // segment end index (base + count)
    __shared__ int s_goff[NTYPES + 1];   // group prefix
    if (threadIdx.x == 0) {
        int g = 0;
        for (int t = 0; t < NTYPES; t++) {
            int h = g_cursor[t];
            s_lim[t] = t * SEG_CAP + h;
            s_goff[t] = g;
            g += (h + GRP - 1) / GRP;
        }
        s_goff[NTYPES] = g;
    }
    __syncthreads();

    const int lane   = threadIdx.x & 31;
    const int wl     = threadIdx.x >> 5;
    const int warp   = (blockIdx.x * blockDim.x + threadIdx.x) >> 5;
    const int nwarps = (gridDim.x * blockDim.x) >> 5;
    const int n_groups = s_goff[NTYPES];
    float2* myh = (float2*)(shh + wl * (GRP * F));   // [GRP][32] float2

    for (int gi = warp; gi < n_groups; gi += nwarps) {
        int t = 0;
        while (gi >= s_goff[t + 1]) t++;
        const int base = t * SEG_CAP + (gi - s_goff[t]) * GRP;
        const int lim  = s_lim[t];

        __syncwarp();   // previous iteration's readers done before overwrite
        int dd[GRP];
        #pragma unroll
        for (int k = 0; k < GRP; k++) {
            int idx = min(base + k, lim - 1);
            int s = __ldg(&g_esrc[idx]);
            dd[k] = __ldg(&g_edst[idx]);
            float sc = rsqrtf(fmaxf(g_deg_out[s], 1.0f));  // broadcast LDG
            float2 v = feat2[s * 32 + lane];
            myh[k * 32 + lane] = make_float2(v.x * sc, v.y * sc);
        }
        __syncwarp();

        const ulonglong2* __restrict__ wv = (const ulonglong2*)(wt + (t << 12));
        const ulonglong2* __restrict__ hp = (const ulonglong2*)myh;  // [GRP][16]
        uint64_t a0[GRP], a1[GRP];
        #pragma unroll
        for (int k = 0; k < GRP; k++) { a0[k] = 0ull; a1[k] = 0ull; }

        #pragma unroll
        for (int j2 = 0; j2 < 16; j2++) {
            const ulonglong2 w0 = wv[(2 * j2) * 32 + lane];       // j = 2*j2
            const ulonglong2 w1 = wv[(2 * j2 + 1) * 32 + lane];   // j = 2*j2+1
            #pragma unroll
            for (int k = 0; k < GRP; k++) {
                const ulonglong2 h = hp[k * 16 + j2];   // h[4j2..4j2+3] broadcast
                asm("fma.rn.f32x2 %0, %1, %2, %0;" : "+l"(a0[k]) : "l"(w0.x), "l"(h.x));
                asm("fma.rn.f32x2 %0, %1, %2, %0;" : "+l"(a1[k]) : "l"(w0.y), "l"(h.x));
                asm("fma.rn.f32x2 %0, %1, %2, %0;" : "+l"(a0[k]) : "l"(w1.x), "l"(h.y));
                asm("fma.rn.f32x2 %0, %1, %2, %0;" : "+l"(a1[k]) : "l"(w1.y), "l"(h.y));
            }
        }

        #pragma unroll
        for (int k = 0; k < GRP; k++) {
            float p, q, r2, s2;
            asm("mov.b64 {%0, %1}, %2;" : "=f"(p),  "=f"(q)  : "l"(a0[k]));
            asm("mov.b64 {%0, %1}, %2;" : "=f"(r2), "=f"(s2) : "l"(a1[k]));
            float ax = p + q;     // output 2L
            float ay = r2 + s2;   // output 2L+1
            float bx = __shfl_down_sync(0xffffffffu, ax, 1);
            float by = __shfl_down_sync(0xffffffffu, ay, 1);
            if ((base + k) < lim && !(lane & 1)) {
                float* ptr = &acc[dd[k] * F + 2 * lane];
                asm volatile("red.global.add.v4.f32 [%0], {%1, %2, %3, %4};"
                             :: "l"(ptr), "f"(ax), "f"(ay), "f"(bx), "f"(by)
                             : "memory");
            }
        }
    }
}

// ------------------------------------------------------------------
// Kernel 4: post-norm by in_deg^{-1/2} + bias (float4 vectorized).
__global__ void rconv_final(float4* __restrict__ out4, const float4* __restrict__ bias4) {
    int i = blockIdx.x * blockDim.x + threadIdx.x;   // over N_NODES*16 float4
    if (i < N_NODES * (F / 4)) {
        int n = i >> 4, f4 = i & 15;
        float s = rsqrtf(fmaxf(g_deg_in[n], 1.0f));
        float4 v = out4[i], b = bias4[f4];
        out4[i] = make_float4(v.x * s + b.x, v.y * s + b.y, v.z * s + b.z, v.w * s + b.w);
    }
}

extern "C" void kernel_launch(void* const* d_in, const int* in_sizes, int n_in,
                              void* d_out, int out_size) {
    const float* feat = (const float*)d_in[0];
    const int*   src  = (const int*)  d_in[1];
    const int*   dst  = (const int*)  d_in[2];
    const int*   ordr = (const int*)  d_in[3];
    const float* emb  = (const float*)d_in[4];
    const float* bias = (const float*)d_in[5];
    float* out = (float*)d_out;

    static bool attr_set = false;
    if (!attr_set) {
        cudaFuncSetAttribute(rconv_edges,
                             cudaFuncAttributeMaxDynamicSharedMemorySize,
                             SMEM_EDGE_BYTES);
        attr_set = true;
    }

    rconv_init<<<256, 256>>>((float4*)out, emb);
    rconv_count_scatter<<<(N_EDGES + 255) / 256, 256>>>(src, dst, ordr);
    rconv_edges<<<148, EDGE_THREADS, SMEM_EDGE_BYTES>>>((const float2*)feat, out);
    rconv_final<<<(N_NODES * (F / 4) + 255) / 256, 256>>>((float4*)out, (const float4*)bias);
}